// round 8
// baseline (speedup 1.0000x reference)
#include <cuda_runtime.h>
#include <math.h>

// B=1024, NL=64, W=2048; inner scan = 62 layers.
#define TMM_B  1024
#define TMM_NL 64
#define TMM_W  2048
#define TMM_NI 62
#define TWO_PI 6.283185307179586f
#define EPS_N  1e-8f
#define EPS_Y  1e-9f

// f32x2-packed 4-scalar recurrence (see R5). R6: each thread computes TWO
// wavelengths (w, w+1024) to (a) provide independent MUFU/FMA chains that
// ride through MUFU-queue backpressure, (b) halve per-output LDS and loop
// overhead. Layer constants collapse to ONE LDS.128/layer: {nd, n, -inv, inv}.

typedef unsigned long long u64;

__device__ __forceinline__ u64 pk2(float lo, float hi) {
    u64 r; asm("mov.b64 %0, {%1, %2};" : "=l"(r) : "f"(lo), "f"(hi)); return r;
}
__device__ __forceinline__ void upk2(u64 v, float& lo, float& hi) {
    asm("mov.b64 {%0, %1}, %2;" : "=f"(lo), "=f"(hi) : "l"(v));
}
__device__ __forceinline__ u64 mul2(u64 a, u64 b) {
    u64 r; asm("mul.rn.f32x2 %0, %1, %2;" : "=l"(r) : "l"(a), "l"(b)); return r;
}
__device__ __forceinline__ u64 fma2(u64 a, u64 b, u64 c) {
    u64 r; asm("fma.rn.f32x2 %0, %1, %2, %3;" : "=l"(r) : "l"(a), "l"(b), "l"(c)); return r;
}

__device__ __forceinline__ float tmm_epilogue(float A, float C, float Bv, float D,
                                              float nin, float nsub)
{
    const float Ae = A + EPS_Y;
    const float t1 = nin * Ae;          // Re(n_in*(E+eps))
    const float t2 = D * nsub;          // Re(H)
    const float t3 = nin * Bv * nsub;   // Im(n_in*(E+eps)); Im(H)=C
    const float nr = t1 - t2;
    const float ni = t3 - C;
    const float dr = t1 + t2;
    const float di = t3 + C;
    return fmaf(nr, nr, ni * ni) / fmaf(dr, dr, di * di);
}

__global__ __launch_bounds__(256)
void tmm_kernel(const float* __restrict__ n_layers,
                const float* __restrict__ d_layers,
                const float* __restrict__ wavelengths,
                float* __restrict__ out)
{
    __shared__ float4 s_q [TMM_NI];   // {n*d, n, -1/(n+e), +1/(n+e)}
    __shared__ float  s_end[2];       // n_in, n_sub

    const int b  = blockIdx.y;
    const int w0 = blockIdx.x * blockDim.x + threadIdx.x;   // 0..1023
    const int w1 = w0 + (TMM_W / 2);                        // 1024..2047

    const float* nrow = n_layers + (size_t)b * TMM_NL;
    const float* drow = d_layers + (size_t)b * TMM_NL;

    for (int i = threadIdx.x; i < TMM_NI; i += blockDim.x) {
        float ni  = nrow[i + 1];
        float di  = drow[i + 1];
        float inv = 1.0f / (ni + EPS_N);
        s_q[i] = make_float4(ni * di, ni, -inv, inv);
    }
    if (threadIdx.x == 0) {
        s_end[0] = nrow[0];
        s_end[1] = nrow[TMM_NL - 1];
    }
    __syncthreads();

    const float k0a = TWO_PI / wavelengths[w0];
    const float k0b = TWO_PI / wavelengths[w1];

    u64 P0 = pk2(1.0f, 0.0f);   // (A, C)  for w0
    u64 Q0 = pk2(0.0f, 1.0f);   // (Bv, D) for w0
    u64 P1 = pk2(1.0f, 0.0f);
    u64 Q1 = pk2(0.0f, 1.0f);

    #pragma unroll 2
    for (int i = 0; i < TMM_NI; i++) {
        const float4 q = s_q[i];          // one LDS.128/layer, both outputs
        float sa, ca, sb, cb;
        __sincosf(q.x * k0a, &sa, &ca);
        __sincosf(q.x * k0b, &sb, &cb);

        const u64 nmn = pk2(q.y, -q.y);   // (n, -n)     NEG on ALU pipe
        const u64 miv = pk2(q.z, q.w);    // (-inv, inv) adjacent regs

        // output 0
        {
            const u64 ss = pk2(sa, sa);
            const u64 cc = pk2(ca, ca);
            const u64 u  = mul2(ss, nmn);
            const u64 v  = mul2(ss, miv);
            const u64 t1 = mul2(Q0, u);
            const u64 t2 = mul2(P0, v);
            P0 = fma2(P0, cc, t1);
            Q0 = fma2(Q0, cc, t2);
        }
        // output 1 (independent chain)
        {
            const u64 ss = pk2(sb, sb);
            const u64 cc = pk2(cb, cb);
            const u64 u  = mul2(ss, nmn);
            const u64 v  = mul2(ss, miv);
            const u64 t1 = mul2(Q1, u);
            const u64 t2 = mul2(P1, v);
            P1 = fma2(P1, cc, t1);
            Q1 = fma2(Q1, cc, t2);
        }
    }

    const float nin  = s_end[0];
    const float nsub = s_end[1];

    float A, C, Bv, D;
    upk2(P0, A, C); upk2(Q0, Bv, D);
    const float R0 = tmm_epilogue(A, C, Bv, D, nin, nsub);
    upk2(P1, A, C); upk2(Q1, Bv, D);
    const float R1 = tmm_epilogue(A, C, Bv, D, nin, nsub);

    float* orow = out + (size_t)b * TMM_W;
    orow[w0] = R0;
    orow[w1] = R1;
}

extern "C" void kernel_launch(void* const* d_in, const int* in_sizes, int n_in,
                              void* d_out, int out_size)
{
    const float* n_layers    = (const float*)d_in[0];
    const float* d_layers    = (const float*)d_in[1];
    const float* wavelengths = (const float*)d_in[2];
    float* out = (float*)d_out;

    dim3 block(256);
    dim3 grid((TMM_W / 2) / 256, TMM_B);   // (4, 1024)
    tmm_kernel<<<grid, block>>>(n_layers, d_layers, wavelengths, out);
}

// round 9
// speedup vs baseline: 1.0829x; 1.0829x over previous
#include <cuda_runtime.h>
#include <math.h>

// B=1024, NL=64, W=2048; inner scan = 62 layers.
#define TMM_B  1024
#define TMM_NL 64
#define TMM_W  2048
#define TMM_NI 62
#define TWO_PI 6.283185307179586f
#define EPS_N  1e-8f
#define EPS_Y  1e-9f

// R8: back to one-output-per-thread (R6 ILP-2 regressed: ptxas held regs=32,
// materialized packing MOVs, ALU busy 3x). Changes vs R5 (72.2us best):
//  - explicit one-layer trig prefetch (double-buffered s/c) + full unroll:
//    layer i+1's MUFU overlaps layer i's packed-FMA tail -> de-convoys warps
//  - __launch_bounds__(256,4): reg ceiling 64 so the pipeline stays in regs
//  - single LDS.128/layer: float4 {n*d, n, -1/(n+e), +1/(n+e)}

typedef unsigned long long u64;

__device__ __forceinline__ u64 pk2(float lo, float hi) {
    u64 r; asm("mov.b64 %0, {%1, %2};" : "=l"(r) : "f"(lo), "f"(hi)); return r;
}
__device__ __forceinline__ void upk2(u64 v, float& lo, float& hi) {
    asm("mov.b64 {%0, %1}, %2;" : "=f"(lo), "=f"(hi) : "l"(v));
}
__device__ __forceinline__ u64 mul2(u64 a, u64 b) {
    u64 r; asm("mul.rn.f32x2 %0, %1, %2;" : "=l"(r) : "l"(a), "l"(b)); return r;
}
__device__ __forceinline__ u64 fma2(u64 a, u64 b, u64 c) {
    u64 r; asm("fma.rn.f32x2 %0, %1, %2, %3;" : "=l"(r) : "l"(a), "l"(b), "l"(c)); return r;
}

__global__ __launch_bounds__(256, 4)
void tmm_kernel(const float* __restrict__ n_layers,
                const float* __restrict__ d_layers,
                const float* __restrict__ wavelengths,
                float* __restrict__ out)
{
    __shared__ float4 s_q [TMM_NI];   // {n*d, n, -1/(n+e), +1/(n+e)}
    __shared__ float  s_end[2];       // n_in, n_sub

    const int b = blockIdx.y;
    const int w = blockIdx.x * blockDim.x + threadIdx.x;

    const float* nrow = n_layers + (size_t)b * TMM_NL;
    const float* drow = d_layers + (size_t)b * TMM_NL;

    for (int i = threadIdx.x; i < TMM_NI; i += blockDim.x) {
        float ni  = nrow[i + 1];
        float di  = drow[i + 1];
        float inv = 1.0f / (ni + EPS_N);
        s_q[i] = make_float4(ni * di, ni, -inv, inv);
    }
    if (threadIdx.x == 0) {
        s_end[0] = nrow[0];
        s_end[1] = nrow[TMM_NL - 1];
    }
    __syncthreads();

    const float k0 = TWO_PI / wavelengths[w];

    u64 P = pk2(1.0f, 0.0f);   // (A, C)
    u64 Q = pk2(0.0f, 1.0f);   // (Bv, D)

    // Prologue: trig for layer 0 in flight before the loop body consumes it.
    float4 q_cur = s_q[0];
    float  s_cur, c_cur;
    __sincosf(q_cur.x * k0, &s_cur, &c_cur);

    #pragma unroll
    for (int i = 0; i < TMM_NI; i++) {
        // Prefetch layer i+1's constants + trig (independent of recurrence).
        float4 q_nxt;
        float  s_nxt, c_nxt;
        if (i + 1 < TMM_NI) {
            q_nxt = s_q[i + 1];
            __sincosf(q_nxt.x * k0, &s_nxt, &c_nxt);
        }

        // Consume layer i.
        const u64 ss  = pk2(s_cur, s_cur);
        const u64 cc  = pk2(c_cur, c_cur);
        const u64 nmn = pk2(q_cur.y, -q_cur.y);   // (n, -n)
        const u64 miv = pk2(q_cur.z, q_cur.w);    // (-inv, inv)

        const u64 u  = mul2(ss, nmn);             // (n*s, -n*s)
        const u64 v  = mul2(ss, miv);             // (-sinv, +sinv)
        const u64 t1 = mul2(Q, u);
        const u64 t2 = mul2(P, v);
        P = fma2(P, cc, t1);
        Q = fma2(Q, cc, t2);

        if (i + 1 < TMM_NI) {
            q_cur = q_nxt; s_cur = s_nxt; c_cur = c_nxt;
        }
    }

    float A, C, Bv, D;
    upk2(P, A, C);
    upk2(Q, Bv, D);

    // E = A + i*Bv*n_sub ; H = D*n_sub + i*C
    // r = (n_in*(E+eps) - H) / (n_in*(E+eps) + H) ; R = |r|^2
    const float nin  = s_end[0];
    const float nsub = s_end[1];
    const float Ae   = A + EPS_Y;

    const float t1 = nin * Ae;
    const float t2 = D * nsub;
    const float t3 = nin * Bv * nsub;

    const float nr = t1 - t2;
    const float ni = t3 - C;
    const float dr = t1 + t2;
    const float di = t3 + C;

    const float R = fmaf(nr, nr, ni * ni) / fmaf(dr, dr, di * di);

    out[(size_t)b * TMM_W + w] = R;
}

extern "C" void kernel_launch(void* const* d_in, const int* in_sizes, int n_in,
                              void* d_out, int out_size)
{
    const float* n_layers    = (const float*)d_in[0];
    const float* d_layers    = (const float*)d_in[1];
    const float* wavelengths = (const float*)d_in[2];
    float* out = (float*)d_out;

    dim3 block(256);
    dim3 grid(TMM_W / 256, TMM_B);   // (8, 1024)
    tmm_kernel<<<grid, block>>>(n_layers, d_layers, wavelengths, out);
}

// round 11
// speedup vs baseline: 1.1460x; 1.0582x over previous
#include <cuda_runtime.h>
#include <math.h>

// B=1024, NL=64, W=2048; inner scan = 62 layers.
#define TMM_B  1024
#define TMM_NL 64
#define TMM_W  2048
#define TMM_NI 62
#define TWO_PI 6.283185307179586f
#define EPS_N  1e-8f
#define EPS_Y  1e-9f

// R9: ILP-2 done right. R5 measured 24.6 cyc/warp-layer vs 16-cyc FMA and
// 16-cyc SFU demands (independent pipes, neither saturated): the gap is
// FMA<->SFU interleave failure within lockstep warps. Two independent
// wavelength chains per thread give every warp FMA work during its own MUFU
// shadow. R6's version of this died at the forced 32-reg budget;
// __launch_bounds__(256,2) lifts the ceiling to 128 so the 8 packed
// accumulators live in regs. Smem layout restored from R5: float4
// {n,-n,-inv,inv} register-aliases the packed multipliers for free.

typedef unsigned long long u64;

__device__ __forceinline__ u64 pk2(float lo, float hi) {
    u64 r; asm("mov.b64 %0, {%1, %2};" : "=l"(r) : "f"(lo), "f"(hi)); return r;
}
__device__ __forceinline__ void upk2(u64 v, float& lo, float& hi) {
    asm("mov.b64 {%0, %1}, %2;" : "=f"(lo), "=f"(hi) : "l"(v));
}
__device__ __forceinline__ u64 mul2(u64 a, u64 b) {
    u64 r; asm("mul.rn.f32x2 %0, %1, %2;" : "=l"(r) : "l"(a), "l"(b)); return r;
}
__device__ __forceinline__ u64 fma2(u64 a, u64 b, u64 c) {
    u64 r; asm("fma.rn.f32x2 %0, %1, %2, %3;" : "=l"(r) : "l"(a), "l"(b), "l"(c)); return r;
}

__device__ __forceinline__ float tmm_epilogue(float A, float C, float Bv, float D,
                                              float nin, float nsub)
{
    const float Ae = A + EPS_Y;
    const float t1 = nin * Ae;
    const float t2 = D * nsub;
    const float t3 = nin * Bv * nsub;
    const float nr = t1 - t2;
    const float ni = t3 - C;
    const float dr = t1 + t2;
    const float di = t3 + C;
    return fmaf(nr, nr, ni * ni) / fmaf(dr, dr, di * di);
}

__global__ __launch_bounds__(256, 2)
void tmm_kernel(const float* __restrict__ n_layers,
                const float* __restrict__ d_layers,
                const float* __restrict__ wavelengths,
                float* __restrict__ out)
{
    __shared__ float  s_nd[TMM_NI];    // n_i * d_i
    __shared__ float4 s_q [TMM_NI];    // {n, -n, -1/(n+e), +1/(n+e)}
    __shared__ float  s_end[2];        // n_in, n_sub

    const int b  = blockIdx.y;
    const int w0 = blockIdx.x * blockDim.x + threadIdx.x;   // 0..1023
    const int w1 = w0 + (TMM_W / 2);                        // 1024..2047

    const float* nrow = n_layers + (size_t)b * TMM_NL;
    const float* drow = d_layers + (size_t)b * TMM_NL;

    for (int i = threadIdx.x; i < TMM_NI; i += blockDim.x) {
        float ni  = nrow[i + 1];
        float di  = drow[i + 1];
        float inv = 1.0f / (ni + EPS_N);
        s_nd[i] = ni * di;
        s_q [i] = make_float4(ni, -ni, -inv, inv);
    }
    if (threadIdx.x == 0) {
        s_end[0] = nrow[0];
        s_end[1] = nrow[TMM_NL - 1];
    }
    __syncthreads();

    const float k0a = TWO_PI / wavelengths[w0];
    const float k0b = TWO_PI / wavelengths[w1];

    u64 P0 = pk2(1.0f, 0.0f);   // (A, C)  chain 0
    u64 Q0 = pk2(0.0f, 1.0f);   // (Bv, D) chain 0
    u64 P1 = pk2(1.0f, 0.0f);   // chain 1
    u64 Q1 = pk2(0.0f, 1.0f);

    #pragma unroll 2
    for (int i = 0; i < TMM_NI; i++) {
        const float nd = s_nd[i];
        const float4 q = s_q[i];            // LDS.128: (n,-n),(-inv,inv) aliased pairs
        const u64 nmn = pk2(q.x, q.y);
        const u64 miv = pk2(q.z, q.w);

        // Both trig issues up front: each chain's FMAs fill the other's MUFU shadow.
        float sa, ca, sb, cb;
        __sincosf(nd * k0a, &sa, &ca);
        __sincosf(nd * k0b, &sb, &cb);

        {
            const u64 ss = pk2(sa, sa);
            const u64 cc = pk2(ca, ca);
            const u64 u  = mul2(ss, nmn);   // (n*s, -n*s)
            const u64 v  = mul2(ss, miv);   // (-sinv, +sinv)
            const u64 t1 = mul2(Q0, u);
            const u64 t2 = mul2(P0, v);
            P0 = fma2(P0, cc, t1);
            Q0 = fma2(Q0, cc, t2);
        }
        {
            const u64 ss = pk2(sb, sb);
            const u64 cc = pk2(cb, cb);
            const u64 u  = mul2(ss, nmn);
            const u64 v  = mul2(ss, miv);
            const u64 t1 = mul2(Q1, u);
            const u64 t2 = mul2(P1, v);
            P1 = fma2(P1, cc, t1);
            Q1 = fma2(Q1, cc, t2);
        }
    }

    const float nin  = s_end[0];
    const float nsub = s_end[1];

    float A, C, Bv, D;
    upk2(P0, A, C); upk2(Q0, Bv, D);
    const float R0 = tmm_epilogue(A, C, Bv, D, nin, nsub);
    upk2(P1, A, C); upk2(Q1, Bv, D);
    const float R1 = tmm_epilogue(A, C, Bv, D, nin, nsub);

    float* orow = out + (size_t)b * TMM_W;
    orow[w0] = R0;
    orow[w1] = R1;
}

extern "C" void kernel_launch(void* const* d_in, const int* in_sizes, int n_in,
                              void* d_out, int out_size)
{
    const float* n_layers    = (const float*)d_in[0];
    const float* d_layers    = (const float*)d_in[1];
    const float* wavelengths = (const float*)d_in[2];
    float* out = (float*)d_out;

    dim3 block(256);
    dim3 grid((TMM_W / 2) / 256, TMM_B);   // (4, 1024)
    tmm_kernel<<<grid, block>>>(n_layers, d_layers, wavelengths, out);
}